// round 1
// baseline (speedup 1.0000x reference)
#include <cuda_runtime.h>
#include <cstdint>

#define HH 512
#define WW 512
#define BB 4
#define NCH 31          // IN_C + DEPTH
#define HW (HH * WW)

// Scratch: feats tensor [B][31][H][W]  (130 MB device global; written before read)
__device__ float g_feats[(size_t)BB * NCH * HW];

// ---------------------------------------------------------------------------
// Init: feats[:,0] = x * sin_w + sin_b   (float4 vectorized)
// ---------------------------------------------------------------------------
__global__ void k_init(const float* __restrict__ x,
                       const float* __restrict__ sin_w,
                       const float* __restrict__ sin_b) {
    int idx = blockIdx.x * blockDim.x + threadIdx.x;   // 0 .. BB*HW/4-1
    float w = sin_w[0], b = sin_b[0];
    int bb = idx >> 16;            // HW/4 = 65536
    int p  = idx & 65535;
    float4 v = reinterpret_cast<const float4*>(x)[idx];
    float4 r = make_float4(fmaf(v.x, w, b), fmaf(v.y, w, b),
                           fmaf(v.z, w, b), fmaf(v.w, w, b));
    reinterpret_cast<float4*>(g_feats)[(size_t)(bb * NCH) * (HW / 4) + p] = r;
}

// ---------------------------------------------------------------------------
// Depth kernel, templated on dilation D.
// Block: 128 threads, output tile 64 wide x 64 tall (thread = 1 column x 32 rows).
// Per channel: stage (64+2D)^2 input tile to smem (cp.async, double-buffered,
// zero-fill for padding), then stream input rows: each (v-D, v0, v+D) triple
// feeds up to 3 output-row accumulators (vertical register reuse).
// ---------------------------------------------------------------------------
template<int D>
__global__ void __launch_bounds__(128)
k_depth(const float* __restrict__ Wmsd,
        const float* __restrict__ bias,
        int di) {
    constexpr int TILE = 64;
    constexpr int RPT  = 32;              // output rows per thread
    constexpr int TW   = TILE + 2 * D;    // staged tile width/height
    constexpr int SBUF = TW * TW;

    extern __shared__ float sbuf[];       // 2 buffers of SBUF floats

    const int nin = di + 1;               // input channels this depth
    const int tid = threadIdx.x;
    const int lx  = tid & 63;             // tile-local x
    const int grp = tid >> 6;             // 0..1 -> row group
    const int bx  = blockIdx.x & 7;
    const int by  = blockIdx.x >> 3;
    const int b   = blockIdx.y;
    const int x0  = bx * TILE, y0 = by * TILE;

    const float* fbase = g_feats + (size_t)b * NCH * HW;
    const int oy0 = grp * RPT;
    const int sx  = lx + D;               // smem x of this thread's column

    float acc[RPT];
    float bi = __ldg(bias + di);
#pragma unroll
    for (int k = 0; k < RPT; k++) acc[k] = bi;

    auto stage = [&](int c, int sel) {
        const float* plane = fbase + (size_t)c * HW;
        float* dst = sbuf + sel * SBUF;
        for (int idx = tid; idx < SBUF; idx += 128) {
            int sy_ = idx / TW;               // TW is constexpr -> cheap
            int sx_ = idx - sy_ * TW;
            int gy  = y0 - D + sy_;
            int gx  = x0 - D + sx_;
            bool ok = ((unsigned)gy < HH) && ((unsigned)gx < WW);
            const float* src = ok ? (plane + gy * WW + gx) : plane;
            unsigned sa = (unsigned)__cvta_generic_to_shared(dst + idx);
            int sz = ok ? 4 : 0;              // zfill handles zero padding
            asm volatile("cp.async.ca.shared.global [%0], [%1], 4, %2;\n"
                         :: "r"(sa), "l"(src), "r"(sz));
        }
        asm volatile("cp.async.commit_group;\n" ::: "memory");
    };

    // Prologue: stage channel 0 into buffer 0
    stage(0, 0);
    asm volatile("cp.async.wait_group 0;\n" ::: "memory");
    __syncthreads();

    int cur = 0;
    for (int c = 0; c < nin; c++) {
        if (c + 1 < nin) stage(c + 1, cur ^ 1);   // overlap next stage with compute

        const float* wp = Wmsd + ((size_t)di * 30 + c) * 9;
        float w0 = __ldg(wp + 0), w1 = __ldg(wp + 1), w2 = __ldg(wp + 2);
        float w3 = __ldg(wp + 3), w4 = __ldg(wp + 4), w5 = __ldg(wp + 5);
        float w6 = __ldg(wp + 6), w7 = __ldg(wp + 7), w8 = __ldg(wp + 8);

        const float* sb_ = sbuf + cur * SBUF;
#pragma unroll
        for (int rr = 0; rr < RPT + 2 * D; rr++) {
            const float* rp = sb_ + (oy0 + rr) * TW + sx;
            float v0 = rp[-D], v1 = rp[0], v2 = rp[D];
            // input row (rel) ir = rr - D contributes to:
            //   out row rr      with weight row 0 (tap at -D)
            //   out row rr - D  with weight row 1 (tap at  0)
            //   out row rr - 2D with weight row 2 (tap at +D)
            if (rr < RPT)
                acc[rr]       = fmaf(w0, v0, fmaf(w1, v1, fmaf(w2, v2, acc[rr])));
            if (rr >= D && rr < RPT + D)
                acc[rr - D]   = fmaf(w3, v0, fmaf(w4, v1, fmaf(w5, v2, acc[rr - D])));
            if (rr >= 2 * D)
                acc[rr - 2*D] = fmaf(w6, v0, fmaf(w7, v1, fmaf(w8, v2, acc[rr - 2*D])));
        }

        if (c + 1 < nin)
            asm volatile("cp.async.wait_group 0;\n" ::: "memory");
        __syncthreads();
        cur ^= 1;
    }

    // ReLU + store new channel (index nin = di+1)
    float* op = g_feats + (size_t)b * NCH * HW + (size_t)nin * HW
              + (size_t)(y0 + oy0) * WW + (x0 + lx);
#pragma unroll
    for (int k = 0; k < RPT; k++)
        op[(size_t)k * WW] = fmaxf(acc[k], 0.0f);
}

// ---------------------------------------------------------------------------
// Final 1x1 conv over 31 channels + convB, then sout affine (float4)
// ---------------------------------------------------------------------------
__global__ void k_final(const float* __restrict__ convW,
                        const float* __restrict__ convB,
                        const float* __restrict__ sout_w,
                        const float* __restrict__ sout_b,
                        float* __restrict__ out) {
    int idx = blockIdx.x * blockDim.x + threadIdx.x;   // 0 .. BB*HW/4-1
    int bb = idx >> 16;
    int p  = idx & 65535;
    const float4* f4 = reinterpret_cast<const float4*>(g_feats)
                     + (size_t)(bb * NCH) * (HW / 4) + p;
    float cb = convB[0];
    float4 a = make_float4(cb, cb, cb, cb);
#pragma unroll 1
    for (int c = 0; c < NCH; c++) {
        float wc = __ldg(convW + c);
        float4 v = __ldg(f4 + (size_t)c * (HW / 4));
        a.x = fmaf(wc, v.x, a.x);
        a.y = fmaf(wc, v.y, a.y);
        a.z = fmaf(wc, v.z, a.z);
        a.w = fmaf(wc, v.w, a.w);
    }
    float sw = sout_w[0], sb = sout_b[0];
    float4 r = make_float4(fmaf(a.x, sw, sb), fmaf(a.y, sw, sb),
                           fmaf(a.z, sw, sb), fmaf(a.w, sw, sb));
    reinterpret_cast<float4*>(out)[idx] = r;
}

// ---------------------------------------------------------------------------
// Launch
// ---------------------------------------------------------------------------
template<int D>
static inline void launch_depth(int i, const float* Wmsd, const float* bias) {
    constexpr int TW = 64 + 2 * D;
    int sm = 2 * TW * TW * (int)sizeof(float);
    cudaFuncSetAttribute(k_depth<D>, cudaFuncAttributeMaxDynamicSharedMemorySize, sm);
    k_depth<D><<<dim3(64, BB), 128, sm>>>(Wmsd, bias, i);
}

extern "C" void kernel_launch(void* const* d_in, const int* in_sizes, int n_in,
                              void* d_out, int out_size) {
    const float* x      = (const float*)d_in[0];
    const float* Wmsd   = (const float*)d_in[1];
    const float* bias   = (const float*)d_in[2];
    const float* convW  = (const float*)d_in[3];
    const float* convB  = (const float*)d_in[4];
    const float* sin_w  = (const float*)d_in[5];
    const float* sin_b  = (const float*)d_in[6];
    const float* sout_w = (const float*)d_in[7];
    const float* sout_b = (const float*)d_in[8];
    float* out = (float*)d_out;

    k_init<<<(BB * HW / 4) / 256, 256>>>(x, sin_w, sin_b);

    for (int i = 0; i < 30; i++) {
        int d = (i % 10) + 1;
        switch (d) {
            case  1: launch_depth< 1>(i, Wmsd, bias); break;
            case  2: launch_depth< 2>(i, Wmsd, bias); break;
            case  3: launch_depth< 3>(i, Wmsd, bias); break;
            case  4: launch_depth< 4>(i, Wmsd, bias); break;
            case  5: launch_depth< 5>(i, Wmsd, bias); break;
            case  6: launch_depth< 6>(i, Wmsd, bias); break;
            case  7: launch_depth< 7>(i, Wmsd, bias); break;
            case  8: launch_depth< 8>(i, Wmsd, bias); break;
            case  9: launch_depth< 9>(i, Wmsd, bias); break;
            default: launch_depth<10>(i, Wmsd, bias); break;
        }
    }

    k_final<<<(BB * HW / 4) / 256, 256>>>(convW, convB, sout_w, sout_b, out);
}

// round 2
// speedup vs baseline: 1.5756x; 1.5756x over previous
#include <cuda_runtime.h>
#include <cstdint>

#define HH 512
#define WW 512
#define BB 4
#define NCH 31          // IN_C + DEPTH
#define HW (HH * WW)

// Scratch: feats tensor [B][31][H][W]  (130 MB device global; written before read)
__device__ float g_feats[(size_t)BB * NCH * HW];

// ---------------------------------------------------------------------------
// Init: feats[:,0] = x * sin_w + sin_b   (float4 vectorized)
// ---------------------------------------------------------------------------
__global__ void k_init(const float* __restrict__ x,
                       const float* __restrict__ sin_w,
                       const float* __restrict__ sin_b) {
    int idx = blockIdx.x * blockDim.x + threadIdx.x;   // 0 .. BB*HW/4-1
    float w = sin_w[0], b = sin_b[0];
    int bb = idx >> 16;            // HW/4 = 65536
    int p  = idx & 65535;
    float4 v = reinterpret_cast<const float4*>(x)[idx];
    float4 r = make_float4(fmaf(v.x, w, b), fmaf(v.y, w, b),
                           fmaf(v.z, w, b), fmaf(v.w, w, b));
    reinterpret_cast<float4*>(g_feats)[(size_t)(bb * NCH) * (HW / 4) + p] = r;
}

// ---------------------------------------------------------------------------
// Depth kernel, templated on dilation D.
// Block: 256 threads, output tile 64 wide x 64 tall.
// Thread = 1 column x 16 rows (4 row groups of 64 columns).
// Staging: fixed 96-float-wide aligned window [x0-16, x0+80) x [y0-D, y0+64+D)
// via 16-byte cp.async (zfill for padding), double-buffered across channels.
// Compute: vertical register window — each loaded (v-D, v0, v+D) triple feeds
// up to 3 output-row accumulators.
// ---------------------------------------------------------------------------
template<int D>
__global__ void __launch_bounds__(256)
k_depth(const float* __restrict__ Wmsd,
        const float* __restrict__ bias,
        int di) {
    constexpr int TILE = 64;
    constexpr int RPT  = 16;              // output rows per thread
    constexpr int TW   = 96;              // staged window width (floats, 16B-aligned)
    constexpr int TH   = TILE + 2 * D;    // staged window height
    constexpr int SBUF = TH * TW;
    constexpr int NV4  = TH * (TW / 4);   // float4 chunks per channel tile

    extern __shared__ float sbuf[];       // 2 buffers of SBUF floats

    const int nin = di + 1;               // input channels this depth
    const int tid = threadIdx.x;
    const int lx  = tid & 63;             // tile-local x (column)
    const int grp = tid >> 6;             // 0..3 -> row group
    const int bx  = blockIdx.x & 7;
    const int by  = blockIdx.x >> 3;
    const int b   = blockIdx.y;
    const int x0  = bx * TILE, y0 = by * TILE;

    const float* fbase = g_feats + (size_t)b * NCH * HW;
    const int oy0 = grp * RPT;
    const int sx  = lx + 16;              // smem x of this thread's column

    float acc[RPT];
    float bi = __ldg(bias + di);
#pragma unroll
    for (int k = 0; k < RPT; k++) acc[k] = bi;

    auto stage = [&](int c, int sel) {
        const float* plane = fbase + (size_t)c * HW;
        float* dst = sbuf + sel * SBUF;
        for (int idx = tid; idx < NV4; idx += 256) {
            int sy_ = idx / (TW / 4);
            int c4  = idx - sy_ * (TW / 4);
            int gy  = y0 - D + sy_;
            int gx  = x0 - 16 + c4 * 4;
            // 4-float chunks are 4-aligned and the image width is a multiple of
            // 4, so a chunk is either fully inside or fully outside -> zfill.
            bool ok = ((unsigned)gy < HH) && ((unsigned)gx < WW);
            const float* src = ok ? (plane + gy * WW + gx) : plane;
            unsigned sa = (unsigned)__cvta_generic_to_shared(dst + sy_ * TW + c4 * 4);
            int sz = ok ? 16 : 0;
            asm volatile("cp.async.cg.shared.global [%0], [%1], 16, %2;\n"
                         :: "r"(sa), "l"(src), "r"(sz));
        }
        asm volatile("cp.async.commit_group;\n" ::: "memory");
    };

    // Prologue: stage channel 0 into buffer 0
    stage(0, 0);
    asm volatile("cp.async.wait_group 0;\n" ::: "memory");
    __syncthreads();

    int cur = 0;
    for (int c = 0; c < nin; c++) {
        if (c + 1 < nin) stage(c + 1, cur ^ 1);   // overlap next stage with compute

        const float* wp = Wmsd + ((size_t)di * 30 + c) * 9;
        float w0 = __ldg(wp + 0), w1 = __ldg(wp + 1), w2 = __ldg(wp + 2);
        float w3 = __ldg(wp + 3), w4 = __ldg(wp + 4), w5 = __ldg(wp + 5);
        float w6 = __ldg(wp + 6), w7 = __ldg(wp + 7), w8 = __ldg(wp + 8);

        const float* sb_ = sbuf + cur * SBUF;
#pragma unroll
        for (int rr = 0; rr < RPT + 2 * D; rr++) {
            const float* rp = sb_ + (oy0 + rr) * TW + sx;
            float v0 = rp[-D], v1 = rp[0], v2 = rp[D];
            // input row (rel) ir = rr - D contributes to:
            //   out row rr      with weight row 0 (tap at -D)
            //   out row rr - D  with weight row 1 (tap at  0)
            //   out row rr - 2D with weight row 2 (tap at +D)
            if (rr < RPT)
                acc[rr]       = fmaf(w0, v0, fmaf(w1, v1, fmaf(w2, v2, acc[rr])));
            if (rr >= D && rr < RPT + D)
                acc[rr - D]   = fmaf(w3, v0, fmaf(w4, v1, fmaf(w5, v2, acc[rr - D])));
            if (rr >= 2 * D)
                acc[rr - 2*D] = fmaf(w6, v0, fmaf(w7, v1, fmaf(w8, v2, acc[rr - 2*D])));
        }

        if (c + 1 < nin)
            asm volatile("cp.async.wait_group 0;\n" ::: "memory");
        __syncthreads();
        cur ^= 1;
    }

    // ReLU + store new channel (index nin = di+1)
    float* op = g_feats + (size_t)b * NCH * HW + (size_t)nin * HW
              + (size_t)(y0 + oy0) * WW + (x0 + lx);
#pragma unroll
    for (int k = 0; k < RPT; k++)
        op[(size_t)k * WW] = fmaxf(acc[k], 0.0f);
}

// ---------------------------------------------------------------------------
// Final 1x1 conv over 31 channels + convB, then sout affine (float4)
// ---------------------------------------------------------------------------
__global__ void k_final(const float* __restrict__ convW,
                        const float* __restrict__ convB,
                        const float* __restrict__ sout_w,
                        const float* __restrict__ sout_b,
                        float* __restrict__ out) {
    int idx = blockIdx.x * blockDim.x + threadIdx.x;   // 0 .. BB*HW/4-1
    int bb = idx >> 16;
    int p  = idx & 65535;
    const float4* f4 = reinterpret_cast<const float4*>(g_feats)
                     + (size_t)(bb * NCH) * (HW / 4) + p;
    float cb = convB[0];
    float4 a = make_float4(cb, cb, cb, cb);
#pragma unroll 4
    for (int c = 0; c < NCH; c++) {
        float wc = __ldg(convW + c);
        float4 v = __ldg(f4 + (size_t)c * (HW / 4));
        a.x = fmaf(wc, v.x, a.x);
        a.y = fmaf(wc, v.y, a.y);
        a.z = fmaf(wc, v.z, a.z);
        a.w = fmaf(wc, v.w, a.w);
    }
    float sw = sout_w[0], sb = sout_b[0];
    float4 r = make_float4(fmaf(a.x, sw, sb), fmaf(a.y, sw, sb),
                           fmaf(a.z, sw, sb), fmaf(a.w, sw, sb));
    reinterpret_cast<float4*>(out)[idx] = r;
}

// ---------------------------------------------------------------------------
// Launch
// ---------------------------------------------------------------------------
template<int D>
static inline void launch_depth(int i, const float* Wmsd, const float* bias) {
    constexpr int TH = 64 + 2 * D;
    int sm = 2 * TH * 96 * (int)sizeof(float);
    cudaFuncSetAttribute(k_depth<D>, cudaFuncAttributeMaxDynamicSharedMemorySize, sm);
    k_depth<D><<<dim3(64, BB), 256, sm>>>(Wmsd, bias, i);
}

extern "C" void kernel_launch(void* const* d_in, const int* in_sizes, int n_in,
                              void* d_out, int out_size) {
    const float* x      = (const float*)d_in[0];
    const float* Wmsd   = (const float*)d_in[1];
    const float* bias   = (const float*)d_in[2];
    const float* convW  = (const float*)d_in[3];
    const float* convB  = (const float*)d_in[4];
    const float* sin_w  = (const float*)d_in[5];
    const float* sin_b  = (const float*)d_in[6];
    const float* sout_w = (const float*)d_in[7];
    const float* sout_b = (const float*)d_in[8];
    float* out = (float*)d_out;

    k_init<<<(BB * HW / 4) / 256, 256>>>(x, sin_w, sin_b);

    for (int i = 0; i < 30; i++) {
        int d = (i % 10) + 1;
        switch (d) {
            case  1: launch_depth< 1>(i, Wmsd, bias); break;
            case  2: launch_depth< 2>(i, Wmsd, bias); break;
            case  3: launch_depth< 3>(i, Wmsd, bias); break;
            case  4: launch_depth< 4>(i, Wmsd, bias); break;
            case  5: launch_depth< 5>(i, Wmsd, bias); break;
            case  6: launch_depth< 6>(i, Wmsd, bias); break;
            case  7: launch_depth< 7>(i, Wmsd, bias); break;
            case  8: launch_depth< 8>(i, Wmsd, bias); break;
            case  9: launch_depth< 9>(i, Wmsd, bias); break;
            default: launch_depth<10>(i, Wmsd, bias); break;
        }
    }

    k_final<<<(BB * HW / 4) / 256, 256>>>(convW, convB, sout_w, sout_b, out);
}